// round 9
// baseline (speedup 1.0000x reference)
#include <cuda_runtime.h>
#include <cstdint>

#define BS 128
#define NR 3
#define CD 64
#define CG 3
#define CH 256
#define KIN 67
#define KTOT 72
#define HW 1024
#define PXT 128
#define THREADS 1024
#define NBLK (BS * HW / PXT)   // 1024

// smem layout (floats)
#define SB_OFF   0          // permuted W1^T tf32: 18432
#define XS_OFF   18432      // X tf32 [3][128 px][76] = 29184 (raw W bounce overlays)
#define W3_OFF   47616      // 256
#define SRED_OFF 47872      // [3][8][128] = 3072
#define WNM_OFF  50944      // [3][128] = 384
#define SMEM_FLOATS 51328
#define SMEM_BYTES (SMEM_FLOATS * 4)   // 205312

#define XSTRIDE 76
#define XREF (PXT * XSTRIDE)   // 9728

__device__ __forceinline__ float tf32f(float f) {
    uint32_t r; asm("cvt.rna.tf32.f32 %0, %1;" : "=r"(r) : "f"(f));
    return __uint_as_float(r);
}

__device__ __forceinline__ void mma8(float* d, const uint32_t* a, uint32_t b0, uint32_t b1) {
    asm volatile(
        "mma.sync.aligned.m16n8k8.row.col.f32.tf32.tf32.f32 "
        "{%0,%1,%2,%3}, {%4,%5,%6,%7}, {%8,%9}, {%0,%1,%2,%3};"
        : "+f"(d[0]), "+f"(d[1]), "+f"(d[2]), "+f"(d[3])
        : "r"(a[0]), "r"(a[1]), "r"(a[2]), "r"(a[3]), "r"(b0), "r"(b1));
}

extern __shared__ float sm[];

__global__ __launch_bounds__(THREADS, 1)
void qnn_kernel(const float* __restrict__ data, const float* __restrict__ gt,
                const float* __restrict__ W1, const float* __restrict__ b1,
                const float* __restrict__ W3, const float* __restrict__ b3,
                float* __restrict__ out)
{
    float* sB   = sm + SB_OFF;
    float* xs   = sm + XS_OFF;
    float* raw  = sm + XS_OFF;      // W bounce, stride 69, overlays xs
    float* w3s  = sm + W3_OFF;
    float* sred = sm + SRED_OFF;
    float* wnm  = sm + WNM_OFF;

    const int tid  = threadIdx.x;
    const int lane = tid & 31;
    const int warp = tid >> 5;       // 0..31
    const int mw = warp & 3;         // px block of 32
    const int no = warp >> 2;        // output eighth: outputs [no*32, no*32+32)
    const int px0 = mw * 32;
    const int r = lane >> 2;         // 0..7
    const int q = lane & 3;          // 0..3
    const int b  = blockIdx.x >> 3;
    const int p0 = (blockIdx.x & 7) * PXT;

    // ---- phase 1: coalesced W1/b1 -> raw[n*69+kk] (conflict-free) ----
    #pragma unroll 1
    for (int it = 0; it < 17; it++) {
        int i = it * THREADS + tid;          // < 256*68 = 17408
        if (i < 256 * 68) {
            int n = i / 68, kk = i - n * 68;
            float v = (kk < KIN) ? W1[n * KIN + kk] : b1[n];
            raw[n * 69 + kk] = tf32f(v);
        }
    }
    if (tid < CH) w3s[tid] = W3[tid];
    __syncthreads();

    // ---- phase 2: n-fastest scatter to permuted sB (conflict-free both sides) ----
    #pragma unroll 1
    for (int it = 0; it < 18; it++) {
        int i = it * THREADS + tid;          // < 256*72 = 18432
        int n = i & 255, kk = i >> 8;
        float v = (kk < 68) ? raw[n * 69 + kk] : 0.f;
        int k8 = kk >> 3, koff = (kk >> 2) & 1, k2 = kk & 3;
        int g = n >> 5, j = (n >> 3) & 3, c = n & 7;
        int blk = (k8 * 2 + koff) * 8 + g;
        sB[(blk * 32 + k2 * 8 + c) * 4 + j] = v;
    }
    const float bias3 = b3[0];
    __syncthreads();    // raw reads done before xs overwrite

    // ---- stage X (3 refs, tf32), bias col 67, zero 68..71 ----
    #pragma unroll 1
    for (int it = 0; it < 27; it++) {
        int i = it * THREADS + tid;          // < 27648
        int n = i / 9216;
        int rem = i - n * 9216;
        int px = rem & 127, k = rem >> 7;    // k 0..71
        float v;
        if (k < CD)       v = data[((size_t)(b * NR + n) * CD + k) * HW + p0 + px];
        else if (k < KIN) v = gt[((size_t)b * CG + (k - CD)) * HW + p0 + px];
        else              v = (k == KIN) ? 1.f : 0.f;
        xs[n * XREF + px * XSTRIDE + k] = tf32f(v);
    }
    __syncthreads();

    // ---- 3 refs: MMA + per-ref epilogue ----
    #pragma unroll 1
    for (int n = 0; n < NR; n++) {
        float acc[2][4][4];
        #pragma unroll
        for (int mt = 0; mt < 2; mt++)
            #pragma unroll
            for (int nt = 0; nt < 4; nt++)
                #pragma unroll
                for (int e = 0; e < 4; e++) acc[mt][nt][e] = 0.f;

        const float* xr = xs + n * XREF;

        #pragma unroll
        for (int k8 = 0; k8 < 9; k8++) {
            uint32_t a[2][4];
            #pragma unroll
            for (int mt = 0; mt < 2; mt++) {
                const float* xrow0 = xr + (px0 + mt * 16 + r) * XSTRIDE + k8 * 8 + q;
                const float* xrow1 = xrow0 + 8 * XSTRIDE;
                a[mt][0] = __float_as_uint(xrow0[0]);
                a[mt][1] = __float_as_uint(xrow1[0]);
                a[mt][2] = __float_as_uint(xrow0[4]);
                a[mt][3] = __float_as_uint(xrow1[4]);
            }
            uint32_t bf[2][4];
            #pragma unroll
            for (int koff = 0; koff < 2; koff++) {
                int blk = (k8 * 2 + koff) * 8 + no;
                float4 v = *(const float4*)(sB + (blk * 32 + q * 8 + r) * 4);
                bf[koff][0] = __float_as_uint(v.x);
                bf[koff][1] = __float_as_uint(v.y);
                bf[koff][2] = __float_as_uint(v.z);
                bf[koff][3] = __float_as_uint(v.w);
            }
            #pragma unroll
            for (int mt = 0; mt < 2; mt++)
                #pragma unroll
                for (int nt = 0; nt < 4; nt++)
                    mma8(acc[mt][nt], a[mt], bf[0][nt], bf[1][nt]);
        }

        // relu * w3 partial sums
        float s[2][2] = {{0.f, 0.f}, {0.f, 0.f}};
        #pragma unroll
        for (int nt = 0; nt < 4; nt++) {
            int n0 = no * 32 + nt * 8 + q * 2;
            float w3a = w3s[n0], w3b = w3s[n0 + 1];
            #pragma unroll
            for (int mt = 0; mt < 2; mt++) {
                s[mt][0] = fmaf(fmaxf(acc[mt][nt][0], 0.f), w3a, s[mt][0]);
                s[mt][0] = fmaf(fmaxf(acc[mt][nt][1], 0.f), w3b, s[mt][0]);
                s[mt][1] = fmaf(fmaxf(acc[mt][nt][2], 0.f), w3a, s[mt][1]);
                s[mt][1] = fmaf(fmaxf(acc[mt][nt][3], 0.f), w3b, s[mt][1]);
            }
        }
        #pragma unroll
        for (int mt = 0; mt < 2; mt++)
            #pragma unroll
            for (int h = 0; h < 2; h++) {
                s[mt][h] += __shfl_xor_sync(0xffffffffu, s[mt][h], 1);
                s[mt][h] += __shfl_xor_sync(0xffffffffu, s[mt][h], 2);
            }
        if (q == 0) {
            #pragma unroll
            for (int mt = 0; mt < 2; mt++)
                #pragma unroll
                for (int h = 0; h < 2; h++)
                    sred[(n * 8 + no) * 128 + px0 + mt * 16 + h * 8 + r] = s[mt][h];
        }
    }
    __syncthreads();

    // ---- sigmoid + normalize + write w ----
    if (tid < 128) {
        int px = tid;
        float t0 = 0.f, t1 = 0.f, t2 = 0.f;
        #pragma unroll
        for (int o8 = 0; o8 < 8; o8++) {
            t0 += sred[(0 * 8 + o8) * 128 + px];
            t1 += sred[(1 * 8 + o8) * 128 + px];
            t2 += sred[(2 * 8 + o8) * 128 + px];
        }
        float g0 = 1.f / (1.f + __expf(-(t0 + bias3)));
        float g1 = 1.f / (1.f + __expf(-(t1 + bias3)));
        float g2 = 1.f / (1.f + __expf(-(t2 + bias3)));
        float inv = 1.f / (g0 + g1 + g2);
        float w0 = g0 * inv, w1 = g1 * inv, w2 = g2 * inv;
        wnm[px] = w0; wnm[128 + px] = w1; wnm[256 + px] = w2;
        float* out_w = out + (size_t)BS * CD * HW;
        out_w[((size_t)b * NR + 0) * HW + p0 + px] = w0;
        out_w[((size_t)b * NR + 1) * HW + p0 + px] = w1;
        out_w[((size_t)b * NR + 2) * HW + p0 + px] = w2;
    }
    __syncthreads();

    // ---- z epilogue: exact fp32 data from gmem (L2-hot), 1024 threads ----
    {
        int px = tid & 127, oct = tid >> 7;   // 8 channels per thread
        float w0 = wnm[px], w1 = wnm[128 + px], w2 = wnm[256 + px];
        const float* dbase = data + (size_t)b * NR * CD * HW + p0 + px;
        float* obase = out + (size_t)b * CD * HW + p0 + px;
        #pragma unroll
        for (int cc = 0; cc < 8; cc++) {
            int c = oct * 8 + cc;
            float z =       dbase[(size_t)(0 * CD + c) * HW] * w0;
            z = fmaf(dbase[(size_t)(1 * CD + c) * HW], w1, z);
            z = fmaf(dbase[(size_t)(2 * CD + c) * HW], w2, z);
            obase[(size_t)c * HW] = z;
        }
    }
}

extern "C" void kernel_launch(void* const* d_in, const int* in_sizes, int n_in,
                              void* d_out, int out_size) {
    const float* data = (const float*)d_in[0];
    const float* gt   = (const float*)d_in[1];
    const float* W1   = (const float*)d_in[2];
    const float* b1   = (const float*)d_in[3];
    const float* W3   = (const float*)d_in[4];
    const float* b3   = (const float*)d_in[5];
    float* out = (float*)d_out;

    cudaFuncSetAttribute(qnn_kernel, cudaFuncAttributeMaxDynamicSharedMemorySize,
                         SMEM_BYTES);
    qnn_kernel<<<NBLK, THREADS, SMEM_BYTES>>>(data, gt, W1, b1, W3, b3, out);
}

// round 10
// speedup vs baseline: 1.3478x; 1.3478x over previous
#include <cuda_runtime.h>
#include <cuda_bf16.h>
#include <cstdint>

#define BS 128
#define NR 3
#define CD 64
#define CG 3
#define CH 256
#define KIN 67
#define KT2 80           // padded k (5 x k16)
#define HW 1024
#define PXT 128
#define THREADS 512
#define NBLK (BS * HW / PXT)   // 1024

#define XSTR 44          // row stride in u32 words (40 data + 4 pad)

// smem (u32 words)
#define SW_OFF   0                    // W bf16 [256][44]   = 11264
#define SX_OFF   11264                // X bf16 [3][128][44]= 16896
#define W3_OFF   28160                // 256 f32
#define SRED_OFF 28416                // [3][4][128] f32 = 1536
#define WNM_OFF  29952                // 384 f32
#define SMEM_U32 30336
#define SMEM_BYTES (SMEM_U32 * 4)     // 121344

__device__ __forceinline__ void mma16(float* d, const uint32_t* a, uint32_t b0, uint32_t b1) {
    asm volatile(
        "mma.sync.aligned.m16n8k16.row.col.f32.bf16.bf16.f32 "
        "{%0,%1,%2,%3}, {%4,%5,%6,%7}, {%8,%9}, {%0,%1,%2,%3};"
        : "+f"(d[0]), "+f"(d[1]), "+f"(d[2]), "+f"(d[3])
        : "r"(a[0]), "r"(a[1]), "r"(a[2]), "r"(a[3]), "r"(b0), "r"(b1));
}

// permuted word position for k in [0,80): fragments become contiguous LDS.64
__device__ __forceinline__ int kpos(int k) {
    int k16 = k >> 4;
    int jj = (k >> 1) & 7;
    return k16 * 8 + ((jj & 3) << 1) + (jj >> 2);
}

extern __shared__ uint32_t smu[];

__global__ __launch_bounds__(THREADS, 1)
void qnn_kernel(const float* __restrict__ data, const float* __restrict__ gt,
                const float* __restrict__ W1, const float* __restrict__ b1,
                const float* __restrict__ W3, const float* __restrict__ b3,
                float* __restrict__ out)
{
    uint32_t* sW = smu + SW_OFF;
    uint32_t* sX = smu + SX_OFF;
    float* w3s  = (float*)(smu + W3_OFF);
    float* sred = (float*)(smu + SRED_OFF);
    float* wnm  = (float*)(smu + WNM_OFF);
    __nv_bfloat16* sh = (__nv_bfloat16*)smu;

    const int tid  = threadIdx.x;
    const int lane = tid & 31;
    const int warp = tid >> 5;       // 0..15
    const int mw = warp & 3;         // px block of 32
    const int nq = warp >> 2;        // output quarter (64 outs)
    const int px0 = mw * 32;
    const int g  = lane >> 2;        // 0..7
    const int tg = lane & 3;         // 0..3
    const int b  = blockIdx.x >> 3;
    const int p0 = (blockIdx.x & 7) * PXT;

    // ---- stage W (bf16, permuted), bias k=67, zero pad ----
    #pragma unroll 1
    for (int it = 0; it < 40; it++) {
        int i = it * THREADS + tid;          // < 256*80
        int n = i / KT2, k = i - n * KT2;
        float v = (k < KIN) ? W1[n * KIN + k] : ((k == KIN) ? b1[n] : 0.f);
        int w = (SW_OFF + n * XSTR + kpos(k)) * 2 + (k & 1);
        sh[w] = __float2bfloat16(v);
    }
    if (tid < CH) w3s[tid] = W3[tid];

    // ---- stage X (3 refs, bf16, permuted) ----
    #pragma unroll 1
    for (int it = 0; it < 60; it++) {
        int i = it * THREADS + tid;          // < 3*80*128
        int px = i & 127;
        int rk = i >> 7;                     // 0..239
        int n = rk / KT2, k = rk - n * KT2;
        float v;
        if (k < CD)       v = data[((size_t)(b * NR + n) * CD + k) * HW + p0 + px];
        else if (k < KIN) v = gt[((size_t)b * CG + (k - CD)) * HW + p0 + px];
        else              v = (k == KIN) ? 1.f : 0.f;
        int w = (SX_OFF + (n * PXT + px) * XSTR + kpos(k)) * 2 + (k & 1);
        sh[w] = __float2bfloat16(v);
    }
    const float bias3 = b3[0];
    __syncthreads();

    // ---- 3 refs: MMA mainloop + per-ref epilogue ----
    #pragma unroll 1
    for (int n = 0; n < NR; n++) {
        float acc[2][8][4];
        #pragma unroll
        for (int mt = 0; mt < 2; mt++)
            #pragma unroll
            for (int nt = 0; nt < 8; nt++)
                #pragma unroll
                for (int e = 0; e < 4; e++) acc[mt][nt][e] = 0.f;

        const uint32_t* xw = sX + n * PXT * XSTR;

        #pragma unroll
        for (int k16 = 0; k16 < 5; k16++) {
            const int kw = k16 * 8 + tg * 2;
            uint32_t a[2][4];
            #pragma unroll
            for (int mt = 0; mt < 2; mt++) {
                int row = px0 + mt * 16 + g;
                uint2 lo = *(const uint2*)(xw + row * XSTR + kw);        // a0,a2
                uint2 hi = *(const uint2*)(xw + (row + 8) * XSTR + kw);  // a1,a3
                a[mt][0] = lo.x; a[mt][2] = lo.y;
                a[mt][1] = hi.x; a[mt][3] = hi.y;
            }
            #pragma unroll
            for (int nt = 0; nt < 8; nt++) {
                int nrow = nq * 64 + nt * 8 + g;
                uint2 bw = *(const uint2*)(sW + nrow * XSTR + kw);       // b0,b1
                mma16(acc[0][nt], a[0], bw.x, bw.y);
                mma16(acc[1][nt], a[1], bw.x, bw.y);
            }
        }

        // relu * w3 partial sums (d0,d1 = row g; d2,d3 = row g+8; cols 2tg,2tg+1)
        float s[2][2] = {{0.f, 0.f}, {0.f, 0.f}};
        #pragma unroll
        for (int nt = 0; nt < 8; nt++) {
            int n0 = nq * 64 + nt * 8 + tg * 2;
            float w3a = w3s[n0], w3b = w3s[n0 + 1];
            #pragma unroll
            for (int mt = 0; mt < 2; mt++) {
                s[mt][0] = fmaf(fmaxf(acc[mt][nt][0], 0.f), w3a, s[mt][0]);
                s[mt][0] = fmaf(fmaxf(acc[mt][nt][1], 0.f), w3b, s[mt][0]);
                s[mt][1] = fmaf(fmaxf(acc[mt][nt][2], 0.f), w3a, s[mt][1]);
                s[mt][1] = fmaf(fmaxf(acc[mt][nt][3], 0.f), w3b, s[mt][1]);
            }
        }
        #pragma unroll
        for (int mt = 0; mt < 2; mt++)
            #pragma unroll
            for (int h = 0; h < 2; h++) {
                s[mt][h] += __shfl_xor_sync(0xffffffffu, s[mt][h], 1);
                s[mt][h] += __shfl_xor_sync(0xffffffffu, s[mt][h], 2);
            }
        if (tg == 0) {
            #pragma unroll
            for (int mt = 0; mt < 2; mt++)
                #pragma unroll
                for (int h = 0; h < 2; h++)
                    sred[(n * 4 + nq) * 128 + px0 + mt * 16 + h * 8 + g] = s[mt][h];
        }
    }
    __syncthreads();

    // ---- sigmoid + normalize + write w ----
    if (tid < 128) {
        int px = tid;
        float t0 = 0.f, t1 = 0.f, t2 = 0.f;
        #pragma unroll
        for (int o4 = 0; o4 < 4; o4++) {
            t0 += sred[(0 * 4 + o4) * 128 + px];
            t1 += sred[(1 * 4 + o4) * 128 + px];
            t2 += sred[(2 * 4 + o4) * 128 + px];
        }
        float g0 = 1.f / (1.f + __expf(-(t0 + bias3)));
        float g1 = 1.f / (1.f + __expf(-(t1 + bias3)));
        float g2 = 1.f / (1.f + __expf(-(t2 + bias3)));
        float inv = 1.f / (g0 + g1 + g2);
        float w0 = g0 * inv, w1 = g1 * inv, w2 = g2 * inv;
        wnm[px] = w0; wnm[128 + px] = w1; wnm[256 + px] = w2;
        float* out_w = out + (size_t)BS * CD * HW;
        out_w[((size_t)b * NR + 0) * HW + p0 + px] = w0;
        out_w[((size_t)b * NR + 1) * HW + p0 + px] = w1;
        out_w[((size_t)b * NR + 2) * HW + p0 + px] = w2;
    }
    __syncthreads();

    // ---- z epilogue: exact fp32 data from gmem (L2-hot) ----
    {
        int px = tid & 127, qtr = tid >> 7;
        float w0 = wnm[px], w1 = wnm[128 + px], w2 = wnm[256 + px];
        const float* dbase = data + (size_t)b * NR * CD * HW + p0 + px;
        float* obase = out + (size_t)b * CD * HW + p0 + px;
        #pragma unroll 4
        for (int cc = 0; cc < 16; cc++) {
            int c = qtr * 16 + cc;
            float z =       dbase[(size_t)(0 * CD + c) * HW] * w0;
            z = fmaf(dbase[(size_t)(1 * CD + c) * HW], w1, z);
            z = fmaf(dbase[(size_t)(2 * CD + c) * HW], w2, z);
            obase[(size_t)c * HW] = z;
        }
    }
}

extern "C" void kernel_launch(void* const* d_in, const int* in_sizes, int n_in,
                              void* d_out, int out_size) {
    const float* data = (const float*)d_in[0];
    const float* gt   = (const float*)d_in[1];
    const float* W1   = (const float*)d_in[2];
    const float* b1   = (const float*)d_in[3];
    const float* W3   = (const float*)d_in[4];
    const float* b3   = (const float*)d_in[5];
    float* out = (float*)d_out;

    cudaFuncSetAttribute(qnn_kernel, cudaFuncAttributeMaxDynamicSharedMemorySize,
                         SMEM_BYTES);
    qnn_kernel<<<NBLK, THREADS, SMEM_BYTES>>>(data, gt, W1, b1, W3, b3, out);
}

// round 11
// speedup vs baseline: 3.9994x; 2.9673x over previous
#include <cuda_runtime.h>
#include <cuda_bf16.h>
#include <cstdint>

#define BS 128
#define NR 3
#define CD 64
#define CG 3
#define CH 256
#define KIN 67
#define HW 1024
#define PXT 128
#define THREADS 512
#define NBLK (BS * HW / PXT)   // 1024

#define XSTR 44          // row stride in u32 words

// smem (u32 words)
#define SW_OFF   0                    // W bf16 [256][44]   = 11264
#define SX_OFF   11264                // X bf16 [3][128][44]= 16896
#define W3_OFF   28160                // 256 f32
#define SRED_OFF 28416                // [3][4][128] f32 = 1536
#define WNM_OFF  29952                // 384 f32
#define SMEM_U32 30336
#define SMEM_BYTES (SMEM_U32 * 4)     // 121344

__device__ __forceinline__ void mma16(float* d, const uint32_t* a, uint32_t b0, uint32_t b1) {
    asm volatile(
        "mma.sync.aligned.m16n8k16.row.col.f32.bf16.bf16.f32 "
        "{%0,%1,%2,%3}, {%4,%5,%6,%7}, {%8,%9}, {%0,%1,%2,%3};"
        : "+f"(d[0]), "+f"(d[1]), "+f"(d[2]), "+f"(d[3])
        : "r"(a[0]), "r"(a[1]), "r"(a[2]), "r"(a[3]), "r"(b0), "r"(b1));
}

__device__ __forceinline__ uint32_t packbf(float lo, float hi) {
    __nv_bfloat162 v = __floats2bfloat162_rn(lo, hi);   // .x = lo (low half)
    return *(uint32_t*)&v;
}
// word wd in [0,32) -> even k it holds (k16 blocks of 8 words, kpos permutation inverse)
__device__ __forceinline__ int wd2k(int wd) {
    int pp = wd & 7;
    int jj = (pp >> 1) + ((pp & 1) << 2);
    return ((wd >> 3) << 4) + (jj << 1);
}

extern __shared__ uint32_t smu[];

__global__ __launch_bounds__(THREADS, 1)
void qnn_kernel(const float* __restrict__ data, const float* __restrict__ gt,
                const float* __restrict__ W1, const float* __restrict__ b1,
                const float* __restrict__ W3, const float* __restrict__ b3,
                float* __restrict__ out)
{
    uint32_t* sW = smu + SW_OFF;
    uint32_t* sX = smu + SX_OFF;
    float* w3s  = (float*)(smu + W3_OFF);
    float* sred = (float*)(smu + SRED_OFF);
    float* wnm  = (float*)(smu + WNM_OFF);

    const int tid  = threadIdx.x;
    const int lane = tid & 31;
    const int warp = tid >> 5;       // 0..15
    const int mw = warp & 3;         // px block of 32
    const int nq = warp >> 2;        // output quarter (64 outs)
    const int px0 = mw * 32;
    const int g  = lane >> 2;        // 0..7
    const int tg = lane & 3;         // 0..3
    const int b  = blockIdx.x >> 3;
    const int p0 = (blockIdx.x & 7) * PXT;

    // ---- stage W main (k<64): 16 word-iters, batch 8 (MLP 8) ----
    #pragma unroll 1
    for (int ot = 0; ot < 2; ot++) {
        uint32_t pv[8]; int sidx[8];
        #pragma unroll
        for (int j = 0; j < 8; j++) {
            int i = (ot * 8 + j) * THREADS + tid;   // < 8192
            int n = i >> 5, wd = i & 31;
            int k = wd2k(wd);
            const float* wp = W1 + n * KIN + k;
            pv[j] = packbf(wp[0], wp[1]);
            sidx[j] = n * XSTR + wd;
        }
        #pragma unroll
        for (int j = 0; j < 8; j++) sW[sidx[j]] = pv[j];
    }
    // ---- W tail: k=64..66, bias k=67, zero words 33,35..39 ----
    if (tid < 256) {
        int n = tid;
        const float* wp = W1 + n * KIN;
        float w64 = wp[64], w65 = wp[65], w66 = wp[66], bb = b1[n];
        uint32_t* row = sW + n * XSTR;
        row[32] = packbf(w64, w65);
        row[34] = packbf(w66, bb);
        row[33] = 0u; row[35] = 0u; row[36] = 0u;
        row[37] = 0u; row[38] = 0u; row[39] = 0u;
        w3s[n] = W3[n];
    }

    // ---- stage X main (k<64): 24 word-iters, batch 8 ----
    #pragma unroll 1
    for (int ot = 0; ot < 3; ot++) {
        uint32_t pv[8]; int sidx[8];
        #pragma unroll
        for (int j = 0; j < 8; j++) {
            int i = (ot * 8 + j) * THREADS + tid;   // < 12288
            int px = i & 127, wd = (i >> 7) & 31, n = i >> 12;
            int k = wd2k(wd);
            const float* dp = data + ((size_t)(b * NR + n) * CD + k) * HW + p0 + px;
            pv[j] = packbf(dp[0], dp[HW]);
            sidx[j] = (n * PXT + px) * XSTR + wd;
        }
        #pragma unroll
        for (int j = 0; j < 8; j++) sX[sidx[j]] = pv[j];
    }
    // ---- X tail: gt (k=64..66) + bias (k=67) + zero pad ----
    if (tid < 384) {
        int n = tid >> 7, px = tid & 127;
        float g0 = gt[((size_t)b * CG + 0) * HW + p0 + px];
        float g1 = gt[((size_t)b * CG + 1) * HW + p0 + px];
        float g2 = gt[((size_t)b * CG + 2) * HW + p0 + px];
        uint32_t* row = sX + (n * PXT + px) * XSTR;
        row[32] = packbf(g0, g1);
        row[34] = packbf(g2, 1.0f);
        row[33] = 0u; row[35] = 0u; row[36] = 0u;
        row[37] = 0u; row[38] = 0u; row[39] = 0u;
    }
    const float bias3 = b3[0];
    __syncthreads();

    // ---- 3 refs: MMA mainloop + per-ref epilogue (unchanged from R10) ----
    #pragma unroll 1
    for (int n = 0; n < NR; n++) {
        float acc[2][8][4];
        #pragma unroll
        for (int mt = 0; mt < 2; mt++)
            #pragma unroll
            for (int nt = 0; nt < 8; nt++)
                #pragma unroll
                for (int e = 0; e < 4; e++) acc[mt][nt][e] = 0.f;

        const uint32_t* xw = sX + n * PXT * XSTR;

        #pragma unroll
        for (int k16 = 0; k16 < 5; k16++) {
            const int kw = k16 * 8 + tg * 2;
            uint32_t a[2][4];
            #pragma unroll
            for (int mt = 0; mt < 2; mt++) {
                int row = px0 + mt * 16 + g;
                uint2 lo = *(const uint2*)(xw + row * XSTR + kw);
                uint2 hi = *(const uint2*)(xw + (row + 8) * XSTR + kw);
                a[mt][0] = lo.x; a[mt][2] = lo.y;
                a[mt][1] = hi.x; a[mt][3] = hi.y;
            }
            #pragma unroll
            for (int nt = 0; nt < 8; nt++) {
                int nrow = nq * 64 + nt * 8 + g;
                uint2 bw = *(const uint2*)(sW + nrow * XSTR + kw);
                mma16(acc[0][nt], a[0], bw.x, bw.y);
                mma16(acc[1][nt], a[1], bw.x, bw.y);
            }
        }

        float s[2][2] = {{0.f, 0.f}, {0.f, 0.f}};
        #pragma unroll
        for (int nt = 0; nt < 8; nt++) {
            int n0 = nq * 64 + nt * 8 + tg * 2;
            float w3a = w3s[n0], w3b = w3s[n0 + 1];
            #pragma unroll
            for (int mt = 0; mt < 2; mt++) {
                s[mt][0] = fmaf(fmaxf(acc[mt][nt][0], 0.f), w3a, s[mt][0]);
                s[mt][0] = fmaf(fmaxf(acc[mt][nt][1], 0.f), w3b, s[mt][0]);
                s[mt][1] = fmaf(fmaxf(acc[mt][nt][2], 0.f), w3a, s[mt][1]);
                s[mt][1] = fmaf(fmaxf(acc[mt][nt][3], 0.f), w3b, s[mt][1]);
            }
        }
        #pragma unroll
        for (int mt = 0; mt < 2; mt++)
            #pragma unroll
            for (int h = 0; h < 2; h++) {
                s[mt][h] += __shfl_xor_sync(0xffffffffu, s[mt][h], 1);
                s[mt][h] += __shfl_xor_sync(0xffffffffu, s[mt][h], 2);
            }
        if (tg == 0) {
            #pragma unroll
            for (int mt = 0; mt < 2; mt++)
                #pragma unroll
                for (int h = 0; h < 2; h++)
                    sred[(n * 4 + nq) * 128 + px0 + mt * 16 + h * 8 + g] = s[mt][h];
        }
    }
    __syncthreads();

    // ---- sigmoid + normalize + write w ----
    if (tid < 128) {
        int px = tid;
        float t0 = 0.f, t1 = 0.f, t2 = 0.f;
        #pragma unroll
        for (int o4 = 0; o4 < 4; o4++) {
            t0 += sred[(0 * 4 + o4) * 128 + px];
            t1 += sred[(1 * 4 + o4) * 128 + px];
            t2 += sred[(2 * 4 + o4) * 128 + px];
        }
        float g0 = 1.f / (1.f + __expf(-(t0 + bias3)));
        float g1 = 1.f / (1.f + __expf(-(t1 + bias3)));
        float g2 = 1.f / (1.f + __expf(-(t2 + bias3)));
        float inv = 1.f / (g0 + g1 + g2);
        float w0 = g0 * inv, w1 = g1 * inv, w2 = g2 * inv;
        wnm[px] = w0; wnm[128 + px] = w1; wnm[256 + px] = w2;
        float* out_w = out + (size_t)BS * CD * HW;
        out_w[((size_t)b * NR + 0) * HW + p0 + px] = w0;
        out_w[((size_t)b * NR + 1) * HW + p0 + px] = w1;
        out_w[((size_t)b * NR + 2) * HW + p0 + px] = w2;
    }
    __syncthreads();

    // ---- z epilogue: batched gmem loads (exact fp32 data) ----
    {
        int px = tid & 127, qtr = tid >> 7;
        float w0 = wnm[px], w1 = wnm[128 + px], w2 = wnm[256 + px];
        const float* dbase = data + (size_t)b * NR * CD * HW + p0 + px;
        float* obase = out + (size_t)b * CD * HW + p0 + px;
        #pragma unroll 1
        for (int half = 0; half < 2; half++) {
            float v0[8], v1[8], v2[8];
            #pragma unroll
            for (int cc = 0; cc < 8; cc++) {
                int c = qtr * 16 + half * 8 + cc;
                v0[cc] = dbase[(size_t)(0 * CD + c) * HW];
                v1[cc] = dbase[(size_t)(1 * CD + c) * HW];
                v2[cc] = dbase[(size_t)(2 * CD + c) * HW];
            }
            #pragma unroll
            for (int cc = 0; cc < 8; cc++) {
                int c = qtr * 16 + half * 8 + cc;
                float z = v0[cc] * w0;
                z = fmaf(v1[cc], w1, z);
                z = fmaf(v2[cc], w2, z);
                obase[(size_t)c * HW] = z;
            }
        }
    }
}

extern "C" void kernel_launch(void* const* d_in, const int* in_sizes, int n_in,
                              void* d_out, int out_size) {
    const float* data = (const float*)d_in[0];
    const float* gt   = (const float*)d_in[1];
    const float* W1   = (const float*)d_in[2];
    const float* b1   = (const float*)d_in[3];
    const float* W3   = (const float*)d_in[4];
    const float* b3   = (const float*)d_in[5];
    float* out = (float*)d_out;

    cudaFuncSetAttribute(qnn_kernel, cudaFuncAttributeMaxDynamicSharedMemorySize,
                         SMEM_BYTES);
    qnn_kernel<<<NBLK, THREADS, SMEM_BYTES>>>(data, gt, W1, b1, W3, b3, out);
}

// round 12
// speedup vs baseline: 4.3787x; 1.0949x over previous
#include <cuda_runtime.h>
#include <cuda_bf16.h>
#include <cstdint>

#define BS 128
#define NR 3
#define CD 64
#define CG 3
#define CH 256
#define KIN 67
#define HW 1024
#define PXT 128
#define THREADS 512
#define NBLK (BS * HW / PXT)   // 1024

#define XSTR 40          // row stride in u32 words — conflict-free per LDS.64 phase

// smem (u32 words)
#define SW_OFF   0                    // W bf16 [256][40]   = 10240
#define SX_OFF   10240                // X bf16 [3][128][40]= 15360
#define W3_OFF   25600                // 256 f32
#define SRED_OFF 25856                // [3][4][128] f32 = 1536
#define WNM_OFF  27392                // 384 f32
#define SMEM_U32 27776
#define SMEM_BYTES (SMEM_U32 * 4)     // 111104

__device__ __forceinline__ void mma16(float* d, const uint32_t* a, uint32_t b0, uint32_t b1) {
    asm volatile(
        "mma.sync.aligned.m16n8k16.row.col.f32.bf16.bf16.f32 "
        "{%0,%1,%2,%3}, {%4,%5,%6,%7}, {%8,%9}, {%0,%1,%2,%3};"
        : "+f"(d[0]), "+f"(d[1]), "+f"(d[2]), "+f"(d[3])
        : "r"(a[0]), "r"(a[1]), "r"(a[2]), "r"(a[3]), "r"(b0), "r"(b1));
}

__device__ __forceinline__ uint32_t packbf(float lo, float hi) {
    __nv_bfloat162 v = __floats2bfloat162_rn(lo, hi);
    return *(uint32_t*)&v;
}
// word wd in [0,32) -> even k it holds
__device__ __forceinline__ int wd2k(int wd) {
    int pp = wd & 7;
    int jj = (pp >> 1) + ((pp & 1) << 2);
    return ((wd >> 3) << 4) + (jj << 1);
}

extern __shared__ uint32_t smu[];

__global__ __launch_bounds__(THREADS, 1)
void qnn_kernel(const float* __restrict__ data, const float* __restrict__ gt,
                const float* __restrict__ W1, const float* __restrict__ b1,
                const float* __restrict__ W3, const float* __restrict__ b3,
                float* __restrict__ out)
{
    uint32_t* sW = smu + SW_OFF;
    uint32_t* sX = smu + SX_OFF;
    float* w3s  = (float*)(smu + W3_OFF);
    float* sred = (float*)(smu + SRED_OFF);
    float* wnm  = (float*)(smu + WNM_OFF);

    const int tid  = threadIdx.x;
    const int lane = tid & 31;
    const int warp = tid >> 5;       // 0..15
    const int mw = warp & 3;         // px block of 32
    const int nq = warp >> 2;        // output quarter (64 outs)
    const int px0 = mw * 32;
    const int g  = lane >> 2;        // 0..7
    const int tg = lane & 3;         // 0..3
    const int b  = blockIdx.x >> 3;
    const int p0 = (blockIdx.x & 7) * PXT;

    // ---- stage W main (k<64): lanes span wd -> STS conflict-free,
    //      LDG = contiguous 256B row segment per warp ----
    {
        const int wd = lane;                       // 0..31
        const int k  = wd2k(wd);
        #pragma unroll 1
        for (int ot = 0; ot < 2; ot++) {
            uint32_t pv[8]; int nn[8];
            #pragma unroll
            for (int j = 0; j < 8; j++) {
                int n = (ot * 8 + j) * 16 + (tid >> 5);   // i>>5
                const float* wp = W1 + n * KIN + k;
                pv[j] = packbf(wp[0], wp[1]);
                nn[j] = n;
            }
            #pragma unroll
            for (int j = 0; j < 8; j++) sW[nn[j] * XSTR + wd] = pv[j];
        }
    }
    // ---- W tail: k=64..67 + zero pad (words 32..39) ----
    if (tid < 256) {
        int n = tid;
        const float* wp = W1 + n * KIN;
        float w64 = wp[64], w65 = wp[65], w66 = wp[66], bb = b1[n];
        uint4 u0, u1;
        u0.x = packbf(w64, w65); u0.y = 0u; u0.z = packbf(w66, bb); u0.w = 0u;
        u1.x = 0u; u1.y = 0u; u1.z = 0u; u1.w = 0u;
        *(uint4*)(sW + n * XSTR + 32) = u0;
        *(uint4*)(sW + n * XSTR + 36) = u1;
        w3s[n] = W3[n];
    }

    // ---- stage X main (k<64): 6 uint4/thread, batched LDG (MLP 24) ----
    #pragma unroll 1
    for (int ot = 0; ot < 2; ot++) {
        float v[3][8]; int rowoff[3];
        #pragma unroll
        for (int j = 0; j < 3; j++) {
            int i = (ot * 3 + j) * THREADS + tid;     // < 3072
            int px = i & 127, q = i >> 7;             // q 0..23
            int n = q >> 3, w4 = q & 7;
            int k0 = (w4 >> 1) * 16 + ((w4 & 1) << 2);
            const float* dp = data + ((size_t)(b * NR + n) * CD + k0) * HW + p0 + px;
            v[j][0] = dp[0];               v[j][1] = dp[(size_t)1 * HW];
            v[j][2] = dp[(size_t)8 * HW];  v[j][3] = dp[(size_t)9 * HW];
            v[j][4] = dp[(size_t)2 * HW];  v[j][5] = dp[(size_t)3 * HW];
            v[j][6] = dp[(size_t)10 * HW]; v[j][7] = dp[(size_t)11 * HW];
            rowoff[j] = (n * PXT + px) * XSTR + w4 * 4;
        }
        #pragma unroll
        for (int j = 0; j < 3; j++) {
            uint4 u;
            u.x = packbf(v[j][0], v[j][1]);
            u.y = packbf(v[j][2], v[j][3]);
            u.z = packbf(v[j][4], v[j][5]);
            u.w = packbf(v[j][6], v[j][7]);
            *(uint4*)(sX + rowoff[j]) = u;
        }
    }
    // ---- X tail: gt (k=64..66) + bias + zero pad ----
    if (tid < 384) {
        int n = tid >> 7, px = tid & 127;
        float g0 = gt[((size_t)b * CG + 0) * HW + p0 + px];
        float g1 = gt[((size_t)b * CG + 1) * HW + p0 + px];
        float g2 = gt[((size_t)b * CG + 2) * HW + p0 + px];
        uint4 u0, u1;
        u0.x = packbf(g0, g1); u0.y = 0u; u0.z = packbf(g2, 1.0f); u0.w = 0u;
        u1.x = 0u; u1.y = 0u; u1.z = 0u; u1.w = 0u;
        uint32_t* row = sX + (n * PXT + px) * XSTR;
        *(uint4*)(row + 32) = u0;
        *(uint4*)(row + 36) = u1;
    }
    const float bias3 = b3[0];
    __syncthreads();

    // ---- 3 refs: MMA mainloop + per-ref epilogue ----
    #pragma unroll 1
    for (int n = 0; n < NR; n++) {
        float acc[2][8][4];
        #pragma unroll
        for (int mt = 0; mt < 2; mt++)
            #pragma unroll
            for (int nt = 0; nt < 8; nt++)
                #pragma unroll
                for (int e = 0; e < 4; e++) acc[mt][nt][e] = 0.f;

        const uint32_t* xw = sX + n * PXT * XSTR + (px0 + g) * XSTR + tg * 2;
        const uint32_t* ww = sW + (nq * 64 + g) * XSTR + tg * 2;

        #pragma unroll
        for (int k16 = 0; k16 < 5; k16++) {
            const int kw = k16 * 8;
            uint32_t a[2][4];
            #pragma unroll
            for (int mt = 0; mt < 2; mt++) {
                uint2 lo = *(const uint2*)(xw + mt * (16 * XSTR) + kw);
                uint2 hi = *(const uint2*)(xw + mt * (16 * XSTR) + 8 * XSTR + kw);
                a[mt][0] = lo.x; a[mt][2] = lo.y;
                a[mt][1] = hi.x; a[mt][3] = hi.y;
            }
            #pragma unroll
            for (int nt = 0; nt < 8; nt++) {
                uint2 bw = *(const uint2*)(ww + nt * (8 * XSTR) + kw);
                mma16(acc[0][nt], a[0], bw.x, bw.y);
                mma16(acc[1][nt], a[1], bw.x, bw.y);
            }
        }

        float s[2][2] = {{0.f, 0.f}, {0.f, 0.f}};
        #pragma unroll
        for (int nt = 0; nt < 8; nt++) {
            int n0 = nq * 64 + nt * 8 + tg * 2;
            float w3a = w3s[n0], w3b = w3s[n0 + 1];
            #pragma unroll
            for (int mt = 0; mt < 2; mt++) {
                s[mt][0] = fmaf(fmaxf(acc[mt][nt][0], 0.f), w3a, s[mt][0]);
                s[mt][0] = fmaf(fmaxf(acc[mt][nt][1], 0.f), w3b, s[mt][0]);
                s[mt][1] = fmaf(fmaxf(acc[mt][nt][2], 0.f), w3a, s[mt][1]);
                s[mt][1] = fmaf(fmaxf(acc[mt][nt][3], 0.f), w3b, s[mt][1]);
            }
        }
        #pragma unroll
        for (int mt = 0; mt < 2; mt++)
            #pragma unroll
            for (int h = 0; h < 2; h++) {
                s[mt][h] += __shfl_xor_sync(0xffffffffu, s[mt][h], 1);
                s[mt][h] += __shfl_xor_sync(0xffffffffu, s[mt][h], 2);
            }
        if (tg == 0) {
            #pragma unroll
            for (int mt = 0; mt < 2; mt++)
                #pragma unroll
                for (int h = 0; h < 2; h++)
                    sred[(n * 4 + nq) * 128 + px0 + mt * 16 + h * 8 + g] = s[mt][h];
        }
    }
    __syncthreads();

    // ---- sigmoid + normalize + write w ----
    if (tid < 128) {
        int px = tid;
        float t0 = 0.f, t1 = 0.f, t2 = 0.f;
        #pragma unroll
        for (int o4 = 0; o4 < 4; o4++) {
            t0 += sred[(0 * 4 + o4) * 128 + px];
            t1 += sred[(1 * 4 + o4) * 128 + px];
            t2 += sred[(2 * 4 + o4) * 128 + px];
        }
        float g0 = 1.f / (1.f + __expf(-(t0 + bias3)));
        float g1 = 1.f / (1.f + __expf(-(t1 + bias3)));
        float g2 = 1.f / (1.f + __expf(-(t2 + bias3)));
        float inv = 1.f / (g0 + g1 + g2);
        float w0 = g0 * inv, w1 = g1 * inv, w2 = g2 * inv;
        wnm[px] = w0; wnm[128 + px] = w1; wnm[256 + px] = w2;
        float* out_w = out + (size_t)BS * CD * HW;
        out_w[((size_t)b * NR + 0) * HW + p0 + px] = w0;
        out_w[((size_t)b * NR + 1) * HW + p0 + px] = w1;
        out_w[((size_t)b * NR + 2) * HW + p0 + px] = w2;
    }
    __syncthreads();

    // ---- z epilogue: batched gmem loads (exact fp32 data) ----
    {
        int px = tid & 127, qtr = tid >> 7;
        float w0 = wnm[px], w1 = wnm[128 + px], w2 = wnm[256 + px];
        const float* dbase = data + (size_t)b * NR * CD * HW + p0 + px;
        float* obase = out + (size_t)b * CD * HW + p0 + px;
        #pragma unroll 1
        for (int half = 0; half < 2; half++) {
            float v0[8], v1[8], v2[8];
            #pragma unroll
            for (int cc = 0; cc < 8; cc++) {
                int c = qtr * 16 + half * 8 + cc;
                v0[cc] = dbase[(size_t)(0 * CD + c) * HW];
                v1[cc] = dbase[(size_t)(1 * CD + c) * HW];
                v2[cc] = dbase[(size_t)(2 * CD + c) * HW];
            }
            #pragma unroll
            for (int cc = 0; cc < 8; cc++) {
                int c = qtr * 16 + half * 8 + cc;
                float z = v0[cc] * w0;
                z = fmaf(v1[cc], w1, z);
                z = fmaf(v2[cc], w2, z);
                obase[(size_t)c * HW] = z;
            }
        }
    }
}

extern "C" void kernel_launch(void* const* d_in, const int* in_sizes, int n_in,
                              void* d_out, int out_size) {
    const float* data = (const float*)d_in[0];
    const float* gt   = (const float*)d_in[1];
    const float* W1   = (const float*)d_in[2];
    const float* b1   = (const float*)d_in[3];
    const float* W3   = (const float*)d_in[4];
    const float* b3   = (const float*)d_in[5];
    float* out = (float*)d_out;

    cudaFuncSetAttribute(qnn_kernel, cudaFuncAttributeMaxDynamicSharedMemorySize,
                         SMEM_BYTES);
    qnn_kernel<<<NBLK, THREADS, SMEM_BYTES>>>(data, gt, W1, b1, W3, b3, out);
}

// round 13
// speedup vs baseline: 4.8638x; 1.1108x over previous
#include <cuda_runtime.h>
#include <cuda_bf16.h>
#include <cstdint>

#define BS 128
#define NR 3
#define CD 64
#define CG 3
#define CH 256
#define KIN 67
#define HW 1024
#define PXT 64
#define THREADS 256
#define NBLK (BS * HW / PXT)   // 2048

#define XSTR 40          // row stride in u32 words — conflict-free per LDS.64 phase

// smem (u32 words)
#define SW_OFF   0                    // W bf16 [256][40]   = 10240
#define SX_OFF   10240                // X bf16 [3][64][40] = 7680
#define W3_OFF   17920                // 256 f32
#define SRED_OFF 18176                // [3][4][64] f32 = 768
#define WNM_OFF  18944                // 192 f32
#define SMEM_U32 19136
#define SMEM_BYTES (SMEM_U32 * 4)     // 76544

__device__ __forceinline__ void mma16(float* d, const uint32_t* a, uint32_t b0, uint32_t b1) {
    asm volatile(
        "mma.sync.aligned.m16n8k16.row.col.f32.bf16.bf16.f32 "
        "{%0,%1,%2,%3}, {%4,%5,%6,%7}, {%8,%9}, {%0,%1,%2,%3};"
        : "+f"(d[0]), "+f"(d[1]), "+f"(d[2]), "+f"(d[3])
        : "r"(a[0]), "r"(a[1]), "r"(a[2]), "r"(a[3]), "r"(b0), "r"(b1));
}

__device__ __forceinline__ uint32_t packbf(float lo, float hi) {
    __nv_bfloat162 v = __floats2bfloat162_rn(lo, hi);
    return *(uint32_t*)&v;
}
// word wd in [0,32) -> even k it holds
__device__ __forceinline__ int wd2k(int wd) {
    int pp = wd & 7;
    int jj = (pp >> 1) + ((pp & 1) << 2);
    return ((wd >> 3) << 4) + (jj << 1);
}

extern __shared__ uint32_t smu[];

__global__ __launch_bounds__(THREADS, 2)
void qnn_kernel(const float* __restrict__ data, const float* __restrict__ gt,
                const float* __restrict__ W1, const float* __restrict__ b1,
                const float* __restrict__ W3, const float* __restrict__ b3,
                float* __restrict__ out)
{
    uint32_t* sW = smu + SW_OFF;
    uint32_t* sX = smu + SX_OFF;
    float* w3s  = (float*)(smu + W3_OFF);
    float* sred = (float*)(smu + SRED_OFF);
    float* wnm  = (float*)(smu + WNM_OFF);

    const int tid  = threadIdx.x;
    const int lane = tid & 31;
    const int warp = tid >> 5;       // 0..7
    const int mw = warp & 1;         // px block of 32
    const int nq = warp >> 1;        // output quarter (64 outs)
    const int px0 = mw * 32;
    const int g  = lane >> 2;        // 0..7
    const int tg = lane & 3;         // 0..3
    const int b  = blockIdx.x >> 4;
    const int p0 = (blockIdx.x & 15) * PXT;

    // ---- stage W main (k<64): wd=lane -> STS conflict-free ----
    {
        const int wd = lane;
        const int k  = wd2k(wd);
        #pragma unroll 1
        for (int ot = 0; ot < 4; ot++) {
            uint32_t pv[8]; int nn[8];
            #pragma unroll
            for (int j = 0; j < 8; j++) {
                int n = (ot * 8 + j) * 8 + warp;
                const float* wp = W1 + n * KIN + k;
                pv[j] = packbf(wp[0], wp[1]);
                nn[j] = n;
            }
            #pragma unroll
            for (int j = 0; j < 8; j++) sW[nn[j] * XSTR + wd] = pv[j];
        }
    }
    // ---- W tail: k=64..67 + zero pad (words 32..39) ----
    {
        int n = tid;
        const float* wp = W1 + n * KIN;
        float w64 = wp[64], w65 = wp[65], w66 = wp[66], bb = b1[n];
        uint4 u0, u1;
        u0.x = packbf(w64, w65); u0.y = 0u; u0.z = packbf(w66, bb); u0.w = 0u;
        u1.x = 0u; u1.y = 0u; u1.z = 0u; u1.w = 0u;
        *(uint4*)(sW + n * XSTR + 32) = u0;
        *(uint4*)(sW + n * XSTR + 36) = u1;
        w3s[n] = W3[n];
    }

    // ---- stage X main (k<64): 6 uint4/thread, batched LDG ----
    #pragma unroll 1
    for (int ot = 0; ot < 2; ot++) {
        float v[3][8]; int rowoff[3];
        #pragma unroll
        for (int j = 0; j < 3; j++) {
            int i = (ot * 3 + j) * THREADS + tid;     // < 1536
            int px = i & 63, q = i >> 6;              // q 0..23
            int n = q >> 3, w4 = q & 7;
            int k0 = (w4 >> 1) * 16 + ((w4 & 1) << 2);
            const float* dp = data + ((size_t)(b * NR + n) * CD + k0) * HW + p0 + px;
            v[j][0] = dp[0];               v[j][1] = dp[(size_t)1 * HW];
            v[j][2] = dp[(size_t)8 * HW];  v[j][3] = dp[(size_t)9 * HW];
            v[j][4] = dp[(size_t)2 * HW];  v[j][5] = dp[(size_t)3 * HW];
            v[j][6] = dp[(size_t)10 * HW]; v[j][7] = dp[(size_t)11 * HW];
            rowoff[j] = (n * PXT + px) * XSTR + w4 * 4;
        }
        #pragma unroll
        for (int j = 0; j < 3; j++) {
            uint4 u;
            u.x = packbf(v[j][0], v[j][1]);
            u.y = packbf(v[j][2], v[j][3]);
            u.z = packbf(v[j][4], v[j][5]);
            u.w = packbf(v[j][6], v[j][7]);
            *(uint4*)(sX + rowoff[j]) = u;
        }
    }
    // ---- X tail: gt (k=64..66) + bias + zero pad ----
    if (tid < 192) {
        int n = tid >> 6, px = tid & 63;
        float g0 = gt[((size_t)b * CG + 0) * HW + p0 + px];
        float g1 = gt[((size_t)b * CG + 1) * HW + p0 + px];
        float g2 = gt[((size_t)b * CG + 2) * HW + p0 + px];
        uint4 u0, u1;
        u0.x = packbf(g0, g1); u0.y = 0u; u0.z = packbf(g2, 1.0f); u0.w = 0u;
        u1.x = 0u; u1.y = 0u; u1.z = 0u; u1.w = 0u;
        uint32_t* row = sX + (n * PXT + px) * XSTR;
        *(uint4*)(row + 32) = u0;
        *(uint4*)(row + 36) = u1;
    }
    const float bias3 = b3[0];
    __syncthreads();

    // ---- 3 refs: MMA mainloop + per-ref epilogue ----
    #pragma unroll 1
    for (int n = 0; n < NR; n++) {
        float acc[2][8][4];
        #pragma unroll
        for (int mt = 0; mt < 2; mt++)
            #pragma unroll
            for (int nt = 0; nt < 8; nt++)
                #pragma unroll
                for (int e = 0; e < 4; e++) acc[mt][nt][e] = 0.f;

        const uint32_t* xw = sX + n * PXT * XSTR + (px0 + g) * XSTR + tg * 2;
        const uint32_t* ww = sW + (nq * 64 + g) * XSTR + tg * 2;

        #pragma unroll
        for (int k16 = 0; k16 < 5; k16++) {
            const int kw = k16 * 8;
            uint32_t a[2][4];
            #pragma unroll
            for (int mt = 0; mt < 2; mt++) {
                uint2 lo = *(const uint2*)(xw + mt * (16 * XSTR) + kw);
                uint2 hi = *(const uint2*)(xw + mt * (16 * XSTR) + 8 * XSTR + kw);
                a[mt][0] = lo.x; a[mt][2] = lo.y;
                a[mt][1] = hi.x; a[mt][3] = hi.y;
            }
            #pragma unroll
            for (int nt = 0; nt < 8; nt++) {
                uint2 bw = *(const uint2*)(ww + nt * (8 * XSTR) + kw);
                mma16(acc[0][nt], a[0], bw.x, bw.y);
                mma16(acc[1][nt], a[1], bw.x, bw.y);
            }
        }

        float s[2][2] = {{0.f, 0.f}, {0.f, 0.f}};
        #pragma unroll
        for (int nt = 0; nt < 8; nt++) {
            int n0 = nq * 64 + nt * 8 + tg * 2;
            float w3a = w3s[n0], w3b = w3s[n0 + 1];
            #pragma unroll
            for (int mt = 0; mt < 2; mt++) {
                s[mt][0] = fmaf(fmaxf(acc[mt][nt][0], 0.f), w3a, s[mt][0]);
                s[mt][0] = fmaf(fmaxf(acc[mt][nt][1], 0.f), w3b, s[mt][0]);
                s[mt][1] = fmaf(fmaxf(acc[mt][nt][2], 0.f), w3a, s[mt][1]);
                s[mt][1] = fmaf(fmaxf(acc[mt][nt][3], 0.f), w3b, s[mt][1]);
            }
        }
        #pragma unroll
        for (int mt = 0; mt < 2; mt++)
            #pragma unroll
            for (int h = 0; h < 2; h++) {
                s[mt][h] += __shfl_xor_sync(0xffffffffu, s[mt][h], 1);
                s[mt][h] += __shfl_xor_sync(0xffffffffu, s[mt][h], 2);
            }
        if (tg == 0) {
            #pragma unroll
            for (int mt = 0; mt < 2; mt++)
                #pragma unroll
                for (int h = 0; h < 2; h++)
                    sred[(n * 4 + nq) * PXT + px0 + mt * 16 + h * 8 + g] = s[mt][h];
        }
    }
    __syncthreads();

    // ---- sigmoid + normalize + write w ----
    if (tid < 64) {
        int px = tid;
        float t0 = 0.f, t1 = 0.f, t2 = 0.f;
        #pragma unroll
        for (int o4 = 0; o4 < 4; o4++) {
            t0 += sred[(0 * 4 + o4) * PXT + px];
            t1 += sred[(1 * 4 + o4) * PXT + px];
            t2 += sred[(2 * 4 + o4) * PXT + px];
        }
        float g0 = 1.f / (1.f + __expf(-(t0 + bias3)));
        float g1 = 1.f / (1.f + __expf(-(t1 + bias3)));
        float g2 = 1.f / (1.f + __expf(-(t2 + bias3)));
        float inv = 1.f / (g0 + g1 + g2);
        float w0 = g0 * inv, w1 = g1 * inv, w2 = g2 * inv;
        wnm[px] = w0; wnm[64 + px] = w1; wnm[128 + px] = w2;
        float* out_w = out + (size_t)BS * CD * HW;
        out_w[((size_t)b * NR + 0) * HW + p0 + px] = w0;
        out_w[((size_t)b * NR + 1) * HW + p0 + px] = w1;
        out_w[((size_t)b * NR + 2) * HW + p0 + px] = w2;
    }
    __syncthreads();

    // ---- z epilogue: batched gmem loads (exact fp32 data) ----
    {
        int px = tid & 63, qtr = tid >> 6;
        float w0 = wnm[px], w1 = wnm[64 + px], w2 = wnm[128 + px];
        const float* dbase = data + (size_t)b * NR * CD * HW + p0 + px;
        float* obase = out + (size_t)b * CD * HW + p0 + px;
        #pragma unroll 1
        for (int half = 0; half < 2; half++) {
            float v0[8], v1[8], v2[8];
            #pragma unroll
            for (int cc = 0; cc < 8; cc++) {
                int c = qtr * 16 + half * 8 + cc;
                v0[cc] = dbase[(size_t)(0 * CD + c) * HW];
                v1[cc] = dbase[(size_t)(1 * CD + c) * HW];
                v2[cc] = dbase[(size_t)(2 * CD + c) * HW];
            }
            #pragma unroll
            for (int cc = 0; cc < 8; cc++) {
                int c = qtr * 16 + half * 8 + cc;
                float z = v0[cc] * w0;
                z = fmaf(v1[cc], w1, z);
                z = fmaf(v2[cc], w2, z);
                obase[(size_t)c * HW] = z;
            }
        }
    }
}

extern "C" void kernel_launch(void* const* d_in, const int* in_sizes, int n_in,
                              void* d_out, int out_size) {
    const float* data = (const float*)d_in[0];
    const float* gt   = (const float*)d_in[1];
    const float* W1   = (const float*)d_in[2];
    const float* b1   = (const float*)d_in[3];
    const float* W3   = (const float*)d_in[4];
    const float* b3   = (const float*)d_in[5];
    float* out = (float*)d_out;

    cudaFuncSetAttribute(qnn_kernel, cudaFuncAttributeMaxDynamicSharedMemorySize,
                         SMEM_BYTES);
    qnn_kernel<<<NBLK, THREADS, SMEM_BYTES>>>(data, gt, W1, b1, W3, b3, out);
}

// round 14
// speedup vs baseline: 4.9188x; 1.0113x over previous
#include <cuda_runtime.h>
#include <cuda_bf16.h>
#include <cstdint>

#define BS 128
#define NR 3
#define CD 64
#define CG 3
#define CH 256
#define KIN 67
#define HW 1024
#define PXT 64
#define THREADS 256
#define NBLK (BS * HW / PXT)   // 2048

#define XSTR 40          // row stride in u32 words — conflict-free per LDS.64 phase

// smem (u32 words)
#define SW_OFF   0                    // W bf16 [256][40]   = 10240
#define SX_OFF   10240                // X bf16 [3][64][40] = 7680
#define W3_OFF   17920                // 256 f32
#define SRED_OFF 18176                // [3][4][64] f32 = 768
#define WNM_OFF  18944                // 192 f32
#define SMEM_U32 19136
#define SMEM_BYTES (SMEM_U32 * 4)     // 76544

__device__ __forceinline__ void mma16(float* d, const uint32_t* a, uint32_t b0, uint32_t b1) {
    asm volatile(
        "mma.sync.aligned.m16n8k16.row.col.f32.bf16.bf16.f32 "
        "{%0,%1,%2,%3}, {%4,%5,%6,%7}, {%8,%9}, {%0,%1,%2,%3};"
        : "+f"(d[0]), "+f"(d[1]), "+f"(d[2]), "+f"(d[3])
        : "r"(a[0]), "r"(a[1]), "r"(a[2]), "r"(a[3]), "r"(b0), "r"(b1));
}

__device__ __forceinline__ uint32_t packbf(float lo, float hi) {
    __nv_bfloat162 v = __floats2bfloat162_rn(lo, hi);
    return *(uint32_t*)&v;
}
// word wd in [0,32) -> even k it holds
__device__ __forceinline__ int wd2k(int wd) {
    int pp = wd & 7;
    int jj = (pp >> 1) + ((pp & 1) << 2);
    return ((wd >> 3) << 4) + (jj << 1);
}

extern __shared__ uint32_t smu[];

__global__ __launch_bounds__(THREADS, 2)
void qnn_kernel(const float* __restrict__ data, const float* __restrict__ gt,
                const float* __restrict__ W1, const float* __restrict__ b1,
                const float* __restrict__ W3, const float* __restrict__ b3,
                float* __restrict__ out)
{
    uint32_t* sW = smu + SW_OFF;
    uint32_t* sX = smu + SX_OFF;
    float* w3s  = (float*)(smu + W3_OFF);
    float* sred = (float*)(smu + SRED_OFF);
    float* wnm  = (float*)(smu + WNM_OFF);

    const int tid  = threadIdx.x;
    const int lane = tid & 31;
    const int warp = tid >> 5;       // 0..7
    const int mw = warp & 1;         // px block of 32
    const int nq = warp >> 1;        // output quarter (64 outs)
    const int px0 = mw * 32;
    const int g  = lane >> 2;        // 0..7
    const int tg = lane & 3;         // 0..3
    const int b  = blockIdx.x >> 4;
    const int p0 = (blockIdx.x & 15) * PXT;

    // ---- stage W main (k<64): wd=lane -> STS conflict-free ----
    {
        const int wd = lane;
        const int k  = wd2k(wd);
        #pragma unroll 1
        for (int ot = 0; ot < 4; ot++) {
            uint32_t pv[8]; int nn[8];
            #pragma unroll
            for (int j = 0; j < 8; j++) {
                int n = (ot * 8 + j) * 8 + warp;
                const float* wp = W1 + n * KIN + k;
                pv[j] = packbf(wp[0], wp[1]);
                nn[j] = n;
            }
            #pragma unroll
            for (int j = 0; j < 8; j++) sW[nn[j] * XSTR + wd] = pv[j];
        }
    }
    // ---- W tail: k=64..67 + zero pad (words 32..39) ----
    {
        int n = tid;
        const float* wp = W1 + n * KIN;
        float w64 = wp[64], w65 = wp[65], w66 = wp[66], bb = b1[n];
        uint4 u0, u1;
        u0.x = packbf(w64, w65); u0.y = 0u; u0.z = packbf(w66, bb); u0.w = 0u;
        u1.x = 0u; u1.y = 0u; u1.z = 0u; u1.w = 0u;
        *(uint4*)(sW + n * XSTR + 32) = u0;
        *(uint4*)(sW + n * XSTR + 36) = u1;
        w3s[n] = W3[n];
    }

    // ---- stage X main (k<64): 6 uint4/thread, batched LDG ----
    #pragma unroll 1
    for (int ot = 0; ot < 2; ot++) {
        float v[3][8]; int rowoff[3];
        #pragma unroll
        for (int j = 0; j < 3; j++) {
            int i = (ot * 3 + j) * THREADS + tid;     // < 1536
            int px = i & 63, q = i >> 6;              // q 0..23
            int n = q >> 3, w4 = q & 7;
            int k0 = (w4 >> 1) * 16 + ((w4 & 1) << 2);
            const float* dp = data + ((size_t)(b * NR + n) * CD + k0) * HW + p0 + px;
            v[j][0] = dp[0];               v[j][1] = dp[(size_t)1 * HW];
            v[j][2] = dp[(size_t)8 * HW];  v[j][3] = dp[(size_t)9 * HW];
            v[j][4] = dp[(size_t)2 * HW];  v[j][5] = dp[(size_t)3 * HW];
            v[j][6] = dp[(size_t)10 * HW]; v[j][7] = dp[(size_t)11 * HW];
            rowoff[j] = (n * PXT + px) * XSTR + w4 * 4;
        }
        #pragma unroll
        for (int j = 0; j < 3; j++) {
            uint4 u;
            u.x = packbf(v[j][0], v[j][1]);
            u.y = packbf(v[j][2], v[j][3]);
            u.z = packbf(v[j][4], v[j][5]);
            u.w = packbf(v[j][6], v[j][7]);
            *(uint4*)(sX + rowoff[j]) = u;
        }
    }
    // ---- X tail: gt (k=64..66) + bias + zero pad ----
    if (tid < 192) {
        int n = tid >> 6, px = tid & 63;
        float g0 = gt[((size_t)b * CG + 0) * HW + p0 + px];
        float g1 = gt[((size_t)b * CG + 1) * HW + p0 + px];
        float g2 = gt[((size_t)b * CG + 2) * HW + p0 + px];
        uint4 u0, u1;
        u0.x = packbf(g0, g1); u0.y = 0u; u0.z = packbf(g2, 1.0f); u0.w = 0u;
        u1.x = 0u; u1.y = 0u; u1.z = 0u; u1.w = 0u;
        uint32_t* row = sX + (n * PXT + px) * XSTR;
        *(uint4*)(row + 32) = u0;
        *(uint4*)(row + 36) = u1;
    }
    const float bias3 = b3[0];
    __syncthreads();

    // ---- 3 refs: MMA mainloop + per-ref epilogue ----
    #pragma unroll 1
    for (int n = 0; n < NR; n++) {
        float acc[2][8][4];
        #pragma unroll
        for (int mt = 0; mt < 2; mt++)
            #pragma unroll
            for (int nt = 0; nt < 8; nt++)
                #pragma unroll
                for (int e = 0; e < 4; e++) acc[mt][nt][e] = 0.f;

        const uint32_t* xw = sX + n * PXT * XSTR + (px0 + g) * XSTR + tg * 2;
        const uint32_t* ww = sW + (nq * 64 + g) * XSTR + tg * 2;

        #pragma unroll
        for (int k16 = 0; k16 < 5; k16++) {
            const int kw = k16 * 8;
            uint32_t a[2][4];
            #pragma unroll
            for (int mt = 0; mt < 2; mt++) {
                uint2 lo = *(const uint2*)(xw + mt * (16 * XSTR) + kw);
                uint2 hi = *(const uint2*)(xw + mt * (16 * XSTR) + 8 * XSTR + kw);
                a[mt][0] = lo.x; a[mt][2] = lo.y;
                a[mt][1] = hi.x; a[mt][3] = hi.y;
            }
            #pragma unroll
            for (int nt = 0; nt < 8; nt++) {
                uint2 bw = *(const uint2*)(ww + nt * (8 * XSTR) + kw);
                mma16(acc[0][nt], a[0], bw.x, bw.y);
                mma16(acc[1][nt], a[1], bw.x, bw.y);
            }
        }

        float s[2][2] = {{0.f, 0.f}, {0.f, 0.f}};
        #pragma unroll
        for (int nt = 0; nt < 8; nt++) {
            int n0 = nq * 64 + nt * 8 + tg * 2;
            float w3a = w3s[n0], w3b = w3s[n0 + 1];
            #pragma unroll
            for (int mt = 0; mt < 2; mt++) {
                s[mt][0] = fmaf(fmaxf(acc[mt][nt][0], 0.f), w3a, s[mt][0]);
                s[mt][0] = fmaf(fmaxf(acc[mt][nt][1], 0.f), w3b, s[mt][0]);
                s[mt][1] = fmaf(fmaxf(acc[mt][nt][2], 0.f), w3a, s[mt][1]);
                s[mt][1] = fmaf(fmaxf(acc[mt][nt][3], 0.f), w3b, s[mt][1]);
            }
        }
        #pragma unroll
        for (int mt = 0; mt < 2; mt++)
            #pragma unroll
            for (int h = 0; h < 2; h++) {
                s[mt][h] += __shfl_xor_sync(0xffffffffu, s[mt][h], 1);
                s[mt][h] += __shfl_xor_sync(0xffffffffu, s[mt][h], 2);
            }
        if (tg == 0) {
            #pragma unroll
            for (int mt = 0; mt < 2; mt++)
                #pragma unroll
                for (int h = 0; h < 2; h++)
                    sred[(n * 4 + nq) * PXT + px0 + mt * 16 + h * 8 + g] = s[mt][h];
        }
    }
    __syncthreads();

    // ---- sigmoid + normalize (store wnm only) ----
    if (tid < 64) {
        int px = tid;
        float t0 = 0.f, t1 = 0.f, t2 = 0.f;
        #pragma unroll
        for (int o4 = 0; o4 < 4; o4++) {
            t0 += sred[(0 * 4 + o4) * PXT + px];
            t1 += sred[(1 * 4 + o4) * PXT + px];
            t2 += sred[(2 * 4 + o4) * PXT + px];
        }
        float g0 = 1.f / (1.f + __expf(-(t0 + bias3)));
        float g1 = 1.f / (1.f + __expf(-(t1 + bias3)));
        float g2 = 1.f / (1.f + __expf(-(t2 + bias3)));
        float inv = 1.f / (g0 + g1 + g2);
        wnm[px] = g0 * inv; wnm[64 + px] = g1 * inv; wnm[128 + px] = g2 * inv;
    }
    __syncthreads();

    // ---- w output: vectorized STG.128 ----
    if (tid < 48) {
        int n = tid >> 4, px4 = tid & 15;
        float4 v = *(const float4*)(wnm + n * 64 + px4 * 4);
        float* out_w = out + (size_t)BS * CD * HW;
        *(float4*)(out_w + ((size_t)b * NR + n) * HW + p0 + px4 * 4) = v;
    }

    // ---- z epilogue: vectorized (float4 over px), exact fp32 data ----
    {
        int px4 = tid & 15, cg = tid >> 4;       // 4 channels per thread
        const float* wb = wnm + px4 * 4;
        float4 w0 = *(const float4*)(wb);
        float4 w1 = *(const float4*)(wb + 64);
        float4 w2 = *(const float4*)(wb + 128);
        const float* dbase = data + ((size_t)(b * NR) * CD + cg * 4) * HW + p0 + px4 * 4;
        float* obase = out + ((size_t)b * CD + cg * 4) * HW + p0 + px4 * 4;
        float4 v0[4], v1[4], v2[4];
        #pragma unroll
        for (int cc = 0; cc < 4; cc++) {
            v0[cc] = *(const float4*)(dbase + (size_t)(0 * CD + cc) * HW);
            v1[cc] = *(const float4*)(dbase + (size_t)(1 * CD + cc) * HW);
            v2[cc] = *(const float4*)(dbase + (size_t)(2 * CD + cc) * HW);
        }
        #pragma unroll
        for (int cc = 0; cc < 4; cc++) {
            float4 z;
            z.x = fmaf(v2[cc].x, w2.x, fmaf(v1[cc].x, w1.x, v0[cc].x * w0.x));
            z.y = fmaf(v2[cc].y, w2.y, fmaf(v1[cc].y, w1.y, v0[cc].y * w0.y));
            z.z = fmaf(v2[cc].z, w2.z, fmaf(v1[cc].z, w1.z, v0[cc].z * w0.z));
            z.w = fmaf(v2[cc].w, w2.w, fmaf(v1[cc].w, w1.w, v0[cc].w * w0.w));
            *(float4*)(obase + (size_t)cc * HW) = z;
        }
    }
}

extern "C" void kernel_launch(void* const* d_in, const int* in_sizes, int n_in,
                              void* d_out, int out_size) {
    const float* data = (const float*)d_in[0];
    const float* gt   = (const float*)d_in[1];
    const float* W1   = (const float*)d_in[2];
    const float* b1   = (const float*)d_in[3];
    const float* W3   = (const float*)d_in[4];
    const float* b3   = (const float*)d_in[5];
    float* out = (float*)d_out;

    cudaFuncSetAttribute(qnn_kernel, cudaFuncAttributeMaxDynamicSharedMemorySize,
                         SMEM_BYTES);
    qnn_kernel<<<NBLK, THREADS, SMEM_BYTES>>>(data, gt, W1, b1, W3, b3, out);
}

// round 15
// speedup vs baseline: 5.1437x; 1.0457x over previous
#include <cuda_runtime.h>
#include <cuda_bf16.h>
#include <cstdint>

#define BS 128
#define NR 3
#define CD 64
#define CG 3
#define CH 256
#define KIN 67
#define HW 1024
#define PXT 64
#define THREADS 256
#define NBLK (BS * HW / PXT)   // 2048

#define XSTR 40          // row stride in u32 words — conflict-free per LDS.64 phase

// smem (u32 words)
#define SW_OFF   0                    // W bf16 [256][40]   = 10240
#define SX_OFF   10240                // X bf16 [3][64][40] = 7680
#define W3_OFF   17920                // 256 f32
#define SRED_OFF 18176                // [3][4][64] f32 = 768
#define WNM_OFF  18944                // 192 f32
#define SMEM_U32 19136
#define SMEM_BYTES (SMEM_U32 * 4)     // 76544

__device__ __forceinline__ void mma16(float* d, const uint32_t* a, uint32_t b0, uint32_t b1) {
    asm volatile(
        "mma.sync.aligned.m16n8k16.row.col.f32.bf16.bf16.f32 "
        "{%0,%1,%2,%3}, {%4,%5,%6,%7}, {%8,%9}, {%0,%1,%2,%3};"
        : "+f"(d[0]), "+f"(d[1]), "+f"(d[2]), "+f"(d[3])
        : "r"(a[0]), "r"(a[1]), "r"(a[2]), "r"(a[3]), "r"(b0), "r"(b1));
}

__device__ __forceinline__ uint32_t packbf(float lo, float hi) {
    __nv_bfloat162 v = __floats2bfloat162_rn(lo, hi);
    return *(uint32_t*)&v;
}
// packed bf16x2 relu
__device__ __forceinline__ uint32_t hmax2z(uint32_t v) {
    uint32_t r;
    asm("max.bf16x2 %0, %1, %2;" : "=r"(r) : "r"(v), "r"(0u));
    return r;
}
// word wd in [0,32) -> even k it holds
__device__ __forceinline__ int wd2k(int wd) {
    int pp = wd & 7;
    int jj = (pp >> 1) + ((pp & 1) << 2);
    return ((wd >> 3) << 4) + (jj << 1);
}

extern __shared__ uint32_t smu[];

__global__ __launch_bounds__(THREADS, 2)
void qnn_kernel(const float* __restrict__ data, const float* __restrict__ gt,
                const float* __restrict__ W1, const float* __restrict__ b1,
                const float* __restrict__ W3, const float* __restrict__ b3,
                float* __restrict__ out)
{
    uint32_t* sW = smu + SW_OFF;
    uint32_t* sX = smu + SX_OFF;
    float* w3s  = (float*)(smu + W3_OFF);
    float* sred = (float*)(smu + SRED_OFF);
    float* wnm  = (float*)(smu + WNM_OFF);

    const int tid  = threadIdx.x;
    const int lane = tid & 31;
    const int warp = tid >> 5;       // 0..7
    const int mw = warp & 1;         // px block of 32
    const int nq = warp >> 1;        // output quarter (64 outs)
    const int px0 = mw * 32;
    const int g  = lane >> 2;        // 0..7
    const int tg = lane & 3;         // 0..3
    const int b  = blockIdx.x >> 4;
    const int p0 = (blockIdx.x & 15) * PXT;

    // ---- stage W main (k<64): wd=lane -> STS conflict-free ----
    {
        const int wd = lane;
        const int k  = wd2k(wd);
        #pragma unroll 1
        for (int ot = 0; ot < 4; ot++) {
            uint32_t pv[8]; int nn[8];
            #pragma unroll
            for (int j = 0; j < 8; j++) {
                int n = (ot * 8 + j) * 8 + warp;
                const float* wp = W1 + n * KIN + k;
                pv[j] = packbf(wp[0], wp[1]);
                nn[j] = n;
            }
            #pragma unroll
            for (int j = 0; j < 8; j++) sW[nn[j] * XSTR + wd] = pv[j];
        }
    }
    // ---- W tail: k=64..67 + zero pad (words 32..39) ----
    {
        int n = tid;
        const float* wp = W1 + n * KIN;
        float w64 = wp[64], w65 = wp[65], w66 = wp[66], bb = b1[n];
        uint4 u0, u1;
        u0.x = packbf(w64, w65); u0.y = 0u; u0.z = packbf(w66, bb); u0.w = 0u;
        u1.x = 0u; u1.y = 0u; u1.z = 0u; u1.w = 0u;
        *(uint4*)(sW + n * XSTR + 32) = u0;
        *(uint4*)(sW + n * XSTR + 36) = u1;
        w3s[n] = W3[n];
    }

    // ---- stage X main (k<64): 6 uint4/thread, batched LDG ----
    #pragma unroll 1
    for (int ot = 0; ot < 2; ot++) {
        float v[3][8]; int rowoff[3];
        #pragma unroll
        for (int j = 0; j < 3; j++) {
            int i = (ot * 3 + j) * THREADS + tid;     // < 1536
            int px = i & 63, q = i >> 6;              // q 0..23
            int n = q >> 3, w4 = q & 7;
            int k0 = (w4 >> 1) * 16 + ((w4 & 1) << 2);
            const float* dp = data + ((size_t)(b * NR + n) * CD + k0) * HW + p0 + px;
            v[j][0] = dp[0];               v[j][1] = dp[(size_t)1 * HW];
            v[j][2] = dp[(size_t)8 * HW];  v[j][3] = dp[(size_t)9 * HW];
            v[j][4] = dp[(size_t)2 * HW];  v[j][5] = dp[(size_t)3 * HW];
            v[j][6] = dp[(size_t)10 * HW]; v[j][7] = dp[(size_t)11 * HW];
            rowoff[j] = (n * PXT + px) * XSTR + w4 * 4;
        }
        #pragma unroll
        for (int j = 0; j < 3; j++) {
            uint4 u;
            u.x = packbf(v[j][0], v[j][1]);
            u.y = packbf(v[j][2], v[j][3]);
            u.z = packbf(v[j][4], v[j][5]);
            u.w = packbf(v[j][6], v[j][7]);
            *(uint4*)(sX + rowoff[j]) = u;
        }
    }
    // ---- X tail: gt (k=64..66) + bias + zero pad ----
    if (tid < 192) {
        int n = tid >> 6, px = tid & 63;
        float g0 = gt[((size_t)b * CG + 0) * HW + p0 + px];
        float g1 = gt[((size_t)b * CG + 1) * HW + p0 + px];
        float g2 = gt[((size_t)b * CG + 2) * HW + p0 + px];
        uint4 u0, u1;
        u0.x = packbf(g0, g1); u0.y = 0u; u0.z = packbf(g2, 1.0f); u0.w = 0u;
        u1.x = 0u; u1.y = 0u; u1.z = 0u; u1.w = 0u;
        uint32_t* row = sX + (n * PXT + px) * XSTR;
        *(uint4*)(row + 32) = u0;
        *(uint4*)(row + 36) = u1;
    }
    const float bias3 = b3[0];
    __syncthreads();

    // ---- precompute w3 B-fragments (replicated over n): 8 regs, once ----
    uint32_t wb[4][2];
    #pragma unroll
    for (int p = 0; p < 4; p++) {
        int o0 = nq * 64 + p * 16 + tg * 2;
        wb[p][0] = packbf(w3s[o0],     w3s[o0 + 1]);
        wb[p][1] = packbf(w3s[o0 + 8], w3s[o0 + 9]);
    }

    // ---- 3 refs: MMA mainloop + MMA-fused epilogue ----
    #pragma unroll 1
    for (int n = 0; n < NR; n++) {
        float acc[2][8][4];
        #pragma unroll
        for (int mt = 0; mt < 2; mt++)
            #pragma unroll
            for (int nt = 0; nt < 8; nt++)
                #pragma unroll
                for (int e = 0; e < 4; e++) acc[mt][nt][e] = 0.f;

        const uint32_t* xw = sX + n * PXT * XSTR + (px0 + g) * XSTR + tg * 2;
        const uint32_t* ww = sW + (nq * 64 + g) * XSTR + tg * 2;

        #pragma unroll
        for (int k16 = 0; k16 < 5; k16++) {
            const int kw = k16 * 8;
            uint32_t a[2][4];
            #pragma unroll
            for (int mt = 0; mt < 2; mt++) {
                uint2 lo = *(const uint2*)(xw + mt * (16 * XSTR) + kw);
                uint2 hi = *(const uint2*)(xw + mt * (16 * XSTR) + 8 * XSTR + kw);
                a[mt][0] = lo.x; a[mt][2] = lo.y;
                a[mt][1] = hi.x; a[mt][3] = hi.y;
            }
            #pragma unroll
            for (int nt = 0; nt < 8; nt++) {
                uint2 bw = *(const uint2*)(ww + nt * (8 * XSTR) + kw);
                mma16(acc[0][nt], a[0], bw.x, bw.y);
                mma16(acc[1][nt], a[1], bw.x, bw.y);
            }
        }

        // ---- epilogue as second MMA: s = relu(acc) @ w3 ----
        float sd[2][4];
        #pragma unroll
        for (int mt = 0; mt < 2; mt++)
            #pragma unroll
            for (int e = 0; e < 4; e++) sd[mt][e] = 0.f;

        #pragma unroll
        for (int p = 0; p < 4; p++) {
            #pragma unroll
            for (int mt = 0; mt < 2; mt++) {
                uint32_t a[4];
                a[0] = hmax2z(packbf(acc[mt][2 * p][0],     acc[mt][2 * p][1]));
                a[1] = hmax2z(packbf(acc[mt][2 * p][2],     acc[mt][2 * p][3]));
                a[2] = hmax2z(packbf(acc[mt][2 * p + 1][0], acc[mt][2 * p + 1][1]));
                a[3] = hmax2z(packbf(acc[mt][2 * p + 1][2], acc[mt][2 * p + 1][3]));
                mma16(sd[mt], a, wb[p][0], wb[p][1]);
            }
        }
        // D cols are replicated -> no shfl; lane tg==0 stores rows g and g+8
        if (tg == 0) {
            #pragma unroll
            for (int mt = 0; mt < 2; mt++) {
                sred[(n * 4 + nq) * PXT + px0 + mt * 16 + g]     = sd[mt][0];
                sred[(n * 4 + nq) * PXT + px0 + mt * 16 + 8 + g] = sd[mt][2];
            }
        }
    }
    __syncthreads();

    // ---- sigmoid + normalize (store wnm only) ----
    if (tid < 64) {
        int px = tid;
        float t0 = 0.f, t1 = 0.f, t2 = 0.f;
        #pragma unroll
        for (int o4 = 0; o4 < 4; o4++) {
            t0 += sred[(0 * 4 + o4) * PXT + px];
            t1 += sred[(1 * 4 + o4) * PXT + px];
            t2 += sred[(2 * 4 + o4) * PXT + px];
        }
        float g0 = 1.f / (1.f + __expf(-(t0 + bias3)));
        float g1 = 1.f / (1.f + __expf(-(t1 + bias3)));
        float g2 = 1.f / (1.f + __expf(-(t2 + bias3)));
        float inv = 1.f / (g0 + g1 + g2);
        wnm[px] = g0 * inv; wnm[64 + px] = g1 * inv; wnm[128 + px] = g2 * inv;
    }
    __syncthreads();

    // ---- w output: vectorized STG.128 ----
    if (tid < 48) {
        int n = tid >> 4, px4 = tid & 15;
        float4 v = *(const float4*)(wnm + n * 64 + px4 * 4);
        float* out_w = out + (size_t)BS * CD * HW;
        *(float4*)(out_w + ((size_t)b * NR + n) * HW + p0 + px4 * 4) = v;
    }

    // ---- z epilogue: vectorized (float4 over px), exact fp32 data ----
    {
        int px4 = tid & 15, cg = tid >> 4;       // 4 channels per thread
        const float* wb4 = wnm + px4 * 4;
        float4 w0 = *(const float4*)(wb4);
        float4 w1 = *(const float4*)(wb4 + 64);
        float4 w2 = *(const float4*)(wb4 + 128);
        const float* dbase = data + ((size_t)(b * NR) * CD + cg * 4) * HW + p0 + px4 * 4;
        float* obase = out + ((size_t)b * CD + cg * 4) * HW + p0 + px4 * 4;
        float4 v0[4], v1[4], v2[4];
        #pragma unroll
        for (int cc = 0; cc < 4; cc++) {
            v0[cc] = *(const float4*)(dbase + (size_t)(0 * CD + cc) * HW);
            v1[cc] = *(const float4*)(dbase + (size_t)(1 * CD + cc) * HW);
            v2[cc] = *(const float4*)(dbase + (size_t)(2 * CD + cc) * HW);
        }
        #pragma unroll
        for (int cc = 0; cc < 4; cc++) {
            float4 z;
            z.x = fmaf(v2[cc].x, w2.x, fmaf(v1[cc].x, w1.x, v0[cc].x * w0.x));
            z.y = fmaf(v2[cc].y, w2.y, fmaf(v1[cc].y, w1.y, v0[cc].y * w0.y));
            z.z = fmaf(v2[cc].z, w2.z, fmaf(v1[cc].z, w1.z, v0[cc].z * w0.z));
            z.w = fmaf(v2[cc].w, w2.w, fmaf(v1[cc].w, w1.w, v0[cc].w * w0.w));
            *(float4*)(obase + (size_t)cc * HW) = z;
        }
    }
}

extern "C" void kernel_launch(void* const* d_in, const int* in_sizes, int n_in,
                              void* d_out, int out_size) {
    const float* data = (const float*)d_in[0];
    const float* gt   = (const float*)d_in[1];
    const float* W1   = (const float*)d_in[2];
    const float* b1   = (const float*)d_in[3];
    const float* W3   = (const float*)d_in[4];
    const float* b3   = (const float*)d_in[5];
    float* out = (float*)d_out;

    cudaFuncSetAttribute(qnn_kernel, cudaFuncAttributeMaxDynamicSharedMemorySize,
                         SMEM_BYTES);
    qnn_kernel<<<NBLK, THREADS, SMEM_BYTES>>>(data, gt, W1, b1, W3, b3, out);
}

// round 16
// speedup vs baseline: 5.4132x; 1.0524x over previous
#include <cuda_runtime.h>
#include <cuda_bf16.h>
#include <cstdint>

#define BS 128
#define NR 3
#define CD 64
#define CG 3
#define CH 256
#define KIN 67
#define HW 1024
#define PXT 64
#define THREADS 256
#define NBLK (BS * HW / PXT)   // 2048

#define XSTR 44          // row stride (u32 words); ldmatrix-phase conflict-free

// smem (u32 words)
#define SW_OFF   0                    // W bf16 [256][44]  = 11264
#define SX_OFF   11264                // X bf16 [3][64][44] = 8448
#define W3_OFF   19712                // 256 f32
#define SRED_OFF 19968                // [3][4][64] f32 = 768
#define WNM_OFF  20736                // 192 f32
#define SMEM_U32 20928
#define SMEM_BYTES (SMEM_U32 * 4)     // 83712

__device__ __forceinline__ void mma16(float* d, const uint32_t* a, uint32_t b0, uint32_t b1) {
    asm volatile(
        "mma.sync.aligned.m16n8k16.row.col.f32.bf16.bf16.f32 "
        "{%0,%1,%2,%3}, {%4,%5,%6,%7}, {%8,%9}, {%0,%1,%2,%3};"
        : "+f"(d[0]), "+f"(d[1]), "+f"(d[2]), "+f"(d[3])
        : "r"(a[0]), "r"(a[1]), "r"(a[2]), "r"(a[3]), "r"(b0), "r"(b1));
}
__device__ __forceinline__ void ldsm4(uint32_t* r, uint32_t addr) {
    asm volatile("ldmatrix.sync.aligned.m8n8.x4.shared.b16 {%0,%1,%2,%3}, [%4];"
        : "=r"(r[0]), "=r"(r[1]), "=r"(r[2]), "=r"(r[3]) : "r"(addr));
}
__device__ __forceinline__ uint32_t packbf(float lo, float hi) {
    __nv_bfloat162 v = __floats2bfloat162_rn(lo, hi);
    return *(uint32_t*)&v;
}
__device__ __forceinline__ uint32_t hmax2z(uint32_t v) {
    uint32_t r;
    asm("max.bf16x2 %0, %1, %2;" : "=r"(r) : "r"(v), "r"(0u));
    return r;
}

extern __shared__ uint32_t smu[];

__global__ __launch_bounds__(THREADS, 2)
void qnn_kernel(const float* __restrict__ data, const float* __restrict__ gt,
                const float* __restrict__ W1, const float* __restrict__ b1,
                const float* __restrict__ W3, const float* __restrict__ b3,
                float* __restrict__ out)
{
    uint32_t* sW = smu + SW_OFF;
    uint32_t* sX = smu + SX_OFF;
    float* w3s  = (float*)(smu + W3_OFF);
    float* sred = (float*)(smu + SRED_OFF);
    float* wnm  = (float*)(smu + WNM_OFF);

    const int tid  = threadIdx.x;
    const int lane = tid & 31;
    const int warp = tid >> 5;       // 0..7
    const int mw = warp & 1;         // px block of 32
    const int nq = warp >> 1;        // output quarter (64 outs)
    const int px0 = mw * 32;
    const int g  = lane >> 2;        // 0..7
    const int tg = lane & 3;         // 0..3
    const int b  = blockIdx.x >> 4;
    const int p0 = (blockIdx.x & 15) * PXT;

    // ---- stage W main (k<64): canonical words, wd=lane -> conflict-free ----
    {
        const int wd = lane;                 // word = k pair (2wd, 2wd+1)
        const float* wbase = W1 + 2 * wd;
        #pragma unroll 1
        for (int ot = 0; ot < 4; ot++) {
            uint32_t pv[8]; int nn[8];
            #pragma unroll
            for (int j = 0; j < 8; j++) {
                int n = (ot * 8 + j) * 8 + warp;
                const float* wp = wbase + n * KIN;
                pv[j] = packbf(wp[0], wp[1]);
                nn[j] = n;
            }
            #pragma unroll
            for (int j = 0; j < 8; j++) sW[nn[j] * XSTR + wd] = pv[j];
        }
    }
    // ---- W tail: k=64..67 + zero pad (words 32..39) ----
    {
        int n = tid;
        const float* wp = W1 + n * KIN;
        float w64 = wp[64], w65 = wp[65], w66 = wp[66], bb = b1[n];
        uint4 u0, u1;
        u0.x = packbf(w64, w65); u0.y = packbf(w66, bb); u0.z = 0u; u0.w = 0u;
        u1.x = 0u; u1.y = 0u; u1.z = 0u; u1.w = 0u;
        *(uint4*)(sW + n * XSTR + 32) = u0;
        *(uint4*)(sW + n * XSTR + 36) = u1;
        w3s[n] = W3[n];
    }

    // ---- stage X main (k<64): canonical, 6 uint4/thread, batched LDG ----
    #pragma unroll 1
    for (int ot = 0; ot < 2; ot++) {
        float v[3][8]; int rowoff[3];
        #pragma unroll
        for (int j = 0; j < 3; j++) {
            int i = (ot * 3 + j) * THREADS + tid;     // < 1536
            int px = i & 63, q = i >> 6;              // q 0..23
            int n = q >> 3, w4 = q & 7;
            int k0 = w4 * 8;
            const float* dp = data + ((size_t)(b * NR + n) * CD + k0) * HW + p0 + px;
            #pragma unroll
            for (int c = 0; c < 8; c++) v[j][c] = dp[(size_t)c * HW];
            rowoff[j] = (n * PXT + px) * XSTR + w4 * 4;
        }
        #pragma unroll
        for (int j = 0; j < 3; j++) {
            uint4 u;
            u.x = packbf(v[j][0], v[j][1]);
            u.y = packbf(v[j][2], v[j][3]);
            u.z = packbf(v[j][4], v[j][5]);
            u.w = packbf(v[j][6], v[j][7]);
            *(uint4*)(sX + rowoff[j]) = u;
        }
    }
    // ---- X tail: gt (k=64..66) + bias + zero pad ----
    if (tid < 192) {
        int n = tid >> 6, px = tid & 63;
        float g0 = gt[((size_t)b * CG + 0) * HW + p0 + px];
        float g1 = gt[((size_t)b * CG + 1) * HW + p0 + px];
        float g2 = gt[((size_t)b * CG + 2) * HW + p0 + px];
        uint4 u0, u1;
        u0.x = packbf(g0, g1); u0.y = packbf(g2, 1.0f); u0.z = 0u; u0.w = 0u;
        u1.x = 0u; u1.y = 0u; u1.z = 0u; u1.w = 0u;
        uint32_t* row = sX + (n * PXT + px) * XSTR;
        *(uint4*)(row + 32) = u0;
        *(uint4*)(row + 36) = u1;
    }
    const float bias3 = b3[0];
    __syncthreads();

    // ---- precompute w3 B-fragments (replicated over n): once ----
    uint32_t wb[4][2];
    #pragma unroll
    for (int p = 0; p < 4; p++) {
        int o0 = nq * 64 + p * 16 + tg * 2;
        wb[p][0] = packbf(w3s[o0],     w3s[o0 + 1]);
        wb[p][1] = packbf(w3s[o0 + 8], w3s[o0 + 9]);
    }

    // ---- ldmatrix lane addresses ----
    uint32_t sb;
    asm("{ .reg .u64 t; cvta.to.shared.u64 t, %1; cvt.u32.u64 %0, t; }"
        : "=r"(sb) : "l"(smu));
    const int t4 = lane >> 3;      // tile index 0..3
    const int lr = lane & 7;       // row within tile
    // A tiles: [r0-7,k0][r8-15,k0][r0-7,k8][r8-15,k8]
    uint32_t aA[2];
    #pragma unroll
    for (int mt = 0; mt < 2; mt++)
        aA[mt] = sb + (uint32_t)((SX_OFF +
                 (px0 + mt * 16 + (t4 & 1) * 8 + lr) * XSTR + (t4 >> 1) * 4) * 4);
    // B tiles for pair j: [nt=2j,k0][nt=2j,k8][nt=2j+1,k0][nt=2j+1,k8]
    uint32_t aB[4];
    #pragma unroll
    for (int j = 0; j < 4; j++)
        aB[j] = sb + (uint32_t)((SW_OFF +
                 (nq * 64 + (j * 2 + (t4 >> 1)) * 8 + lr) * XSTR + (t4 & 1) * 4) * 4);

    // ---- 3 refs: ldmatrix+MMA mainloop + MMA-fused epilogue ----
    #pragma unroll 1
    for (int n = 0; n < NR; n++) {
        float acc[2][8][4];
        #pragma unroll
        for (int mt = 0; mt < 2; mt++)
            #pragma unroll
            for (int nt = 0; nt < 8; nt++)
                #pragma unroll
                for (int e = 0; e < 4; e++) acc[mt][nt][e] = 0.f;

        uint32_t ar0 = aA[0] + (uint32_t)(n * (PXT * XSTR * 4));
        uint32_t ar1 = aA[1] + (uint32_t)(n * (PXT * XSTR * 4));
        uint32_t br0 = aB[0], br1 = aB[1], br2 = aB[2], br3 = aB[3];

        #pragma unroll
        for (int k16 = 0; k16 < 5; k16++) {
            uint32_t a[2][4];
            ldsm4(a[0], ar0);  ar0 += 32;
            ldsm4(a[1], ar1);  ar1 += 32;
            uint32_t bf[8][2];
            {
                uint32_t bt[4];
                ldsm4(bt, br0);  br0 += 32;
                bf[0][0] = bt[0]; bf[0][1] = bt[1]; bf[1][0] = bt[2]; bf[1][1] = bt[3];
                ldsm4(bt, br1);  br1 += 32;
                bf[2][0] = bt[0]; bf[2][1] = bt[1]; bf[3][0] = bt[2]; bf[3][1] = bt[3];
                ldsm4(bt, br2);  br2 += 32;
                bf[4][0] = bt[0]; bf[4][1] = bt[1]; bf[5][0] = bt[2]; bf[5][1] = bt[3];
                ldsm4(bt, br3);  br3 += 32;
                bf[6][0] = bt[0]; bf[6][1] = bt[1]; bf[7][0] = bt[2]; bf[7][1] = bt[3];
            }
            #pragma unroll
            for (int nt = 0; nt < 8; nt++) {
                mma16(acc[0][nt], a[0], bf[nt][0], bf[nt][1]);
                mma16(acc[1][nt], a[1], bf[nt][0], bf[nt][1]);
            }
        }

        // ---- epilogue as second MMA: s = relu(acc) @ w3 ----
        float sd[2][4];
        #pragma unroll
        for (int mt = 0; mt < 2; mt++)
            #pragma unroll
            for (int e = 0; e < 4; e++) sd[mt][e] = 0.f;

        #pragma unroll
        for (int p = 0; p < 4; p++) {
            #pragma unroll
            for (int mt = 0; mt < 2; mt++) {
                uint32_t a[4];
                a[0] = hmax2z(packbf(acc[mt][2 * p][0],     acc[mt][2 * p][1]));
                a[1] = hmax2z(packbf(acc[mt][2 * p][2],     acc[mt][2 * p][3]));
                a[2] = hmax2z(packbf(acc[mt][2 * p + 1][0], acc[mt][2 * p + 1][1]));
                a[3] = hmax2z(packbf(acc[mt][2 * p + 1][2], acc[mt][2 * p + 1][3]));
                mma16(sd[mt], a, wb[p][0], wb[p][1]);
            }
        }
        if (tg == 0) {
            #pragma unroll
            for (int mt = 0; mt < 2; mt++) {
                sred[(n * 4 + nq) * PXT + px0 + mt * 16 + g]     = sd[mt][0];
                sred[(n * 4 + nq) * PXT + px0 + mt * 16 + 8 + g] = sd[mt][2];
            }
        }
    }
    __syncthreads();

    // ---- sigmoid + normalize ----
    if (tid < 64) {
        int px = tid;
        float t0 = 0.f, t1 = 0.f, t2 = 0.f;
        #pragma unroll
        for (int o4 = 0; o4 < 4; o4++) {
            t0 += sred[(0 * 4 + o4) * PXT + px];
            t1 += sred[(1 * 4 + o4) * PXT + px];
            t2 += sred[(2 * 4 + o4) * PXT + px];
        }
        float g0 = 1.f / (1.f + __expf(-(t0 + bias3)));
        float g1 = 1.f / (1.f + __expf(-(t1 + bias3)));
        float g2 = 1.f / (1.f + __expf(-(t2 + bias3)));
        float inv = 1.f / (g0 + g1 + g2);
        wnm[px] = g0 * inv; wnm[64 + px] = g1 * inv; wnm[128 + px] = g2 * inv;
    }
    __syncthreads();

    // ---- w output: vectorized STG.128 ----
    if (tid < 48) {
        int n = tid >> 4, px4 = tid & 15;
        float4 v = *(const float4*)(wnm + n * 64 + px4 * 4);
        float* out_w = out + (size_t)BS * CD * HW;
        *(float4*)(out_w + ((size_t)b * NR + n) * HW + p0 + px4 * 4) = v;
    }

    // ---- z epilogue: vectorized (float4 over px), exact fp32 data ----
    {
        int px4 = tid & 15, cg = tid >> 4;       // 4 channels per thread
        const float* wb4 = wnm + px4 * 4;
        float4 w0 = *(const float4*)(wb4);
        float4 w1 = *(const float4*)(wb4 + 64);
        float4 w2 = *(const float4*)(wb4 + 128);
        const float* dbase = data + ((size_t)(b * NR) * CD + cg * 4) * HW + p0 + px4 * 4;
        float* obase = out + ((size_t)b * CD + cg * 4) * HW + p0 + px4 * 4;
        float4 v0[4], v1[4], v2[4];
        #pragma unroll
        for (int cc = 0; cc < 4; cc++) {
            v0[cc] = *(const float4*)(dbase + (size_t)(0 * CD + cc) * HW);
            v1[cc] = *(const float4*)(dbase + (size_t)(1 * CD + cc) * HW);
            v2[cc] = *(const float4*)(dbase + (size_t)(2 * CD + cc) * HW);
        }
        #pragma unroll
        for (int cc = 0; cc < 4; cc++) {
            float4 z;
            z.x = fmaf(v2[cc].x, w2.x, fmaf(v1[cc].x, w1.x, v0[cc].x * w0.x));
            z.y = fmaf(v2[cc].y, w2.y, fmaf(v1[cc].y, w1.y, v0[cc].y * w0.y));
            z.z = fmaf(v2[cc].z, w2.z, fmaf(v1[cc].z, w1.z, v0[cc].z * w0.z));
            z.w = fmaf(v2[cc].w, w2.w, fmaf(v1[cc].w, w1.w, v0[cc].w * w0.w));
            *(float4*)(obase + (size_t)cc * HW) = z;
        }
    }
}

extern "C" void kernel_launch(void* const* d_in, const int* in_sizes, int n_in,
                              void* d_out, int out_size) {
    const float* data = (const float*)d_in[0];
    const float* gt   = (const float*)d_in[1];
    const float* W1   = (const float*)d_in[2];
    const float* b1   = (const float*)d_in[3];
    const float* W3   = (const float*)d_in[4];
    const float* b3   = (const float*)d_in[5];
    float* out = (float*)d_out;

    cudaFuncSetAttribute(qnn_kernel, cudaFuncAttributeMaxDynamicSharedMemorySize,
                         SMEM_BYTES);
    qnn_kernel<<<NBLK, THREADS, SMEM_BYTES>>>(data, gt, W1, b1, W3, b3, out);
}